// round 10
// baseline (speedup 1.0000x reference)
#include <cuda_runtime.h>
#include <cuda_bf16.h>
#include <cstdint>

#define EMB   1024
#define NHEAD 16
#define HDIM  64
#define BATCH 4
#define SEQ   2048
#define MTOT  (BATCH*SEQ)

// GEMM tensor-core config
#define GKC        64                 // K elements per chunk (64 bf16 = 128B = SW128 row)
#define TILE_B     16384              // one 128x64 bf16 tile
#define STAGE_B    (4*TILE_B)         // Ah, Al, Bh, Bl
#define GSMEM      (1024 + 2*STAGE_B) // 132096 bytes

// Attention config
#define AQ 128            // q rows per CTA
#define AK 128            // keys per tile
#define NT (SEQ/AK)       // 16 tiles
// attention smem offsets (bytes). K double-buffered, V single, P single.
#define A_HMAX    64       // float[2][128]
#define A_HSUM    1088     // float[2][128]
#define A_QH      3072
#define A_QL      (A_QH  + 16384)
#define A_K0      (A_QL  + 16384)    // stage0: KH, KL
#define A_K1      (A_K0  + 32768)    // stage1: KH, KL
#define A_VTH     (A_K1  + 32768)
#define A_VTL     (A_VTH + 16384)
#define A_PH      (A_VTL + 16384)
#define A_PL      (A_PH  + 32768)
#define ASMEM     (A_PL  + 32768)    // 199680

// Scratch (device-global: allocation-guard-safe)
__device__ float g_q[MTOT*EMB];
__device__ float g_k[MTOT*EMB];
__device__ float g_v[MTOT*EMB];
__device__ float g_ctx[MTOT*EMB];

__device__ __forceinline__ float ex2f(float x) {
    float y; asm("ex2.approx.ftz.f32 %0, %1;" : "=f"(y) : "f"(x)); return y;
}

// HAS_TCGEN05 is 1 in the host pass (parses, never assembles) and in the
// compute_103a device pass. It is 0 ONLY in non-feature device passes
// (e.g. compute_103), which must never see tcgen05 asm (ptxas rejects it).
#if defined(__CUDA_ARCH_FEAT_SM103_ALL) || !defined(__CUDA_ARCH__)
#define HAS_TCGEN05 1
#else
#define HAS_TCGEN05 0
#endif

#if HAS_TCGEN05
// ---------------- tcgen05 helpers (parsed on host; emitted only on sm_103a) ----
__device__ __forceinline__ uint32_t elect_one() {
    uint32_t pr;
    asm volatile("{\n\t.reg .pred p;\n\telect.sync _|p, 0xFFFFFFFF;\n\t"
                 "selp.b32 %0, 1, 0, p;\n\t}" : "=r"(pr));
    return pr;
}
__device__ __forceinline__ uint64_t mkdesc(uint32_t addr) {  // SW128, LBO=1, SBO=64
    const uint64_t base = (uint64_t(2) << 61) | (uint64_t(1) << 46)
                        | (uint64_t(64) << 32) | (uint64_t(1) << 16);
    return base | ((uint64_t)(addr >> 4) & 0x3FFF);
}
__device__ __forceinline__ void mma_f16_ss(uint32_t d, uint64_t ad, uint64_t bd,
                                           uint32_t idesc, uint32_t en) {
    asm volatile("{\n\t.reg .pred p;\n\tsetp.ne.u32 p, %5, 0;\n\t"
        "tcgen05.mma.cta_group::1.kind::f16 [%0], %1, %2, %3, {%4,%4,%4,%4}, p;\n\t}"
        :: "r"(d), "l"(ad), "l"(bd), "r"(idesc), "r"(0u), "r"(en) : "memory");
}
#define TC_COMMIT(a) \
    asm volatile("tcgen05.commit.cta_group::1.mbarrier::arrive::one.shared::cluster.b64 [%0];" \
                 :: "r"(a) : "memory")
#define TC_ALLOC(sres, n) \
    asm volatile("tcgen05.alloc.cta_group::1.sync.aligned.shared::cta.b32 [%0], %1;" \
                 :: "r"(sres), "r"((uint32_t)(n)) : "memory")
#define TC_DEALLOC(tm, n) \
    asm volatile("tcgen05.dealloc.cta_group::1.sync.aligned.b32 %0, %1;" :: "r"(tm), "r"((uint32_t)(n)))
#define TC_RELINQ() asm volatile("tcgen05.relinquish_alloc_permit.cta_group::1.sync.aligned;")
#define TC_FENCE_AFTER()  asm volatile("tcgen05.fence::after_thread_sync;" ::: "memory")
#define TC_FENCE_BEFORE() asm volatile("tcgen05.fence::before_thread_sync;" ::: "memory")
#define TC_WAIT_LD() asm volatile("tcgen05.wait::ld.sync.aligned;" ::: "memory")
#define LDTM_X32(r, a) \
    asm volatile("tcgen05.ld.sync.aligned.32x32b.x32.b32 "                        \
        "{%0,%1,%2,%3,%4,%5,%6,%7,%8,%9,%10,%11,%12,%13,%14,%15,"                 \
        "%16,%17,%18,%19,%20,%21,%22,%23,%24,%25,%26,%27,%28,%29,%30,%31}, [%32];"\
        : "=r"((r)[0]),"=r"((r)[1]),"=r"((r)[2]),"=r"((r)[3]),                    \
          "=r"((r)[4]),"=r"((r)[5]),"=r"((r)[6]),"=r"((r)[7]),                    \
          "=r"((r)[8]),"=r"((r)[9]),"=r"((r)[10]),"=r"((r)[11]),                  \
          "=r"((r)[12]),"=r"((r)[13]),"=r"((r)[14]),"=r"((r)[15]),                \
          "=r"((r)[16]),"=r"((r)[17]),"=r"((r)[18]),"=r"((r)[19]),                \
          "=r"((r)[20]),"=r"((r)[21]),"=r"((r)[22]),"=r"((r)[23]),                \
          "=r"((r)[24]),"=r"((r)[25]),"=r"((r)[26]),"=r"((r)[27]),                \
          "=r"((r)[28]),"=r"((r)[29]),"=r"((r)[30]),"=r"((r)[31])                 \
        : "r"(a))
#endif // HAS_TCGEN05 helpers

// ---- arch-independent helpers ----
__device__ __forceinline__ uint32_t smem_u32(const void* p) {
    uint32_t a;
    asm("{ .reg .u64 t; cvta.to.shared.u64 t, %1; cvt.u32.u64 %0, t; }"
        : "=r"(a) : "l"(p));
    return a;
}
#define MBAR_INIT(a, n) \
    asm volatile("mbarrier.init.shared.b64 [%0], %1;" :: "r"(a), "r"(n) : "memory")
#define MBAR_WAIT(a, par) do {                                                    \
    uint32_t _m = (a), _p = (par), _d;                                            \
    asm volatile("{\n\t.reg .pred p;\n\t"                                         \
        "mbarrier.try_wait.parity.acquire.cta.shared::cta.b64 p, [%1], %2;\n\t"   \
        "selp.b32 %0, 1, 0, p;\n\t}" : "=r"(_d) : "r"(_m), "r"(_p) : "memory");   \
    if (!_d) {                                                                    \
        asm volatile("{\n\t.reg .pred P1;\n\tWL_%=:\n\t"                          \
            "mbarrier.try_wait.parity.acquire.cta.shared::cta.b64 P1, [%0], %1, 0x989680;\n\t" \
            "@P1 bra.uni WD_%=;\n\tbra.uni WL_%=;\n\tWD_%=:\n\t}"                 \
            :: "r"(_m), "r"(_p) : "memory");                                      \
    } } while (0)
#define FENCE_PROXY() asm volatile("fence.proxy.async.shared::cta;" ::: "memory")

__device__ __forceinline__ uint32_t pk2(__nv_bfloat16 lo, __nv_bfloat16 hi) {
    return (uint32_t)__bfloat16_as_ushort(lo) | ((uint32_t)__bfloat16_as_ushort(hi) << 16);
}

// idescs: F32 acc, BF16 a/b, M=128
#define GIDESC   ((1u<<4)|(1u<<7)|(1u<<10)|((128u/8)<<17)|((128u/16)<<24))  // N=128
#define IDESC_PV ((1u<<4)|(1u<<7)|(1u<<10)|(( 64u/8)<<17)|((128u/16)<<24))  // N=64

// ---------------------------------------------------------------------------
// C[M,N] = A[M,K] * W[N,K]^T  (unchanged — validated tcgen05 path)
// ---------------------------------------------------------------------------
__global__ void __launch_bounds__(256, 1)
gemm_tc_kernel(const float* __restrict__ A, const float* __restrict__ W,
               float* __restrict__ C) {
    extern __shared__ __align__(1024) char smem[];
    const int t = threadIdx.x;
    const int bm = blockIdx.y << 7, bn = blockIdx.x << 7;

#if HAS_TCGEN05
    const uint32_t sb = smem_u32(smem);
    const int wid = t >> 5, lane = t & 31;
    const uint32_t TMP   = sb;
    const uint32_t MB0   = sb + 16;
    const uint32_t MB1   = sb + 24;
    const uint32_t TILES = sb + 1024;

    if (t == 0) { MBAR_INIT(MB0, 1); MBAR_INIT(MB1, 1); }
    if (wid == 0) TC_ALLOC(TMP, 128);
    __syncthreads();
    uint32_t tmem;
    asm volatile("ld.shared.b32 %0, [%1];" : "=r"(tmem) : "r"(TMP));

    int ph0 = 0, ph1 = 0;

    for (int c = 0; c < EMB / GKC; c++) {
        const int buf = c & 1;
        if (c >= 2) {
            if (buf == 0) { MBAR_WAIT(MB0, ph0 & 1); ph0++; }
            else          { MBAR_WAIT(MB1, ph1 & 1); ph1++; }
        }
        const uint32_t stage = TILES + buf * STAGE_B;
#pragma unroll
        for (int it = 0; it < 8; it++) {
            int idx = it * 256 + t;
            int row = idx >> 4, g4 = idx & 15;
            float4 av = *(const float4*)(A + (size_t)(bm + row) * EMB + c * GKC + g4 * 4);
            float4 wv = *(const float4*)(W + (size_t)(bn + row) * EMB + c * GKC + g4 * 4);
            uint32_t off = row * 128 + g4 * 8;
            uint32_t sw  = off ^ ((off >> 3) & 0x70);
            float af[4] = {av.x, av.y, av.z, av.w};
            float wf[4] = {wv.x, wv.y, wv.z, wv.w};
            __nv_bfloat16 ah[4], al[4], wh[4], wl[4];
#pragma unroll
            for (int u = 0; u < 4; u++) {
                ah[u] = __float2bfloat16(af[u]);
                al[u] = __float2bfloat16(af[u] - __bfloat162float(ah[u]));
                wh[u] = __float2bfloat16(wf[u]);
                wl[u] = __float2bfloat16(wf[u] - __bfloat162float(wh[u]));
            }
            char* stp = smem + (stage - sb);
            *(uint2*)(stp + 0 * TILE_B + sw) = make_uint2(pk2(ah[0], ah[1]), pk2(ah[2], ah[3]));
            *(uint2*)(stp + 1 * TILE_B + sw) = make_uint2(pk2(al[0], al[1]), pk2(al[2], al[3]));
            *(uint2*)(stp + 2 * TILE_B + sw) = make_uint2(pk2(wh[0], wh[1]), pk2(wh[2], wh[3]));
            *(uint2*)(stp + 3 * TILE_B + sw) = make_uint2(pk2(wl[0], wl[1]), pk2(wl[2], wl[3]));
        }
        FENCE_PROXY();
        __syncthreads();

        if (wid == 0 && elect_one()) {
            uint64_t dAh = mkdesc(stage + 0 * TILE_B);
            uint64_t dAl = mkdesc(stage + 1 * TILE_B);
            uint64_t dBh = mkdesc(stage + 2 * TILE_B);
            uint64_t dBl = mkdesc(stage + 3 * TILE_B);
#pragma unroll
            for (int ks = 0; ks < 4; ks++) {
                uint32_t en0 = !(c == 0 && ks == 0);
                mma_f16_ss(tmem, dAh + ks * 2, dBh + ks * 2, GIDESC, en0);
                mma_f16_ss(tmem, dAh + ks * 2, dBl + ks * 2, GIDESC, 1u);
                mma_f16_ss(tmem, dAl + ks * 2, dBh + ks * 2, GIDESC, 1u);
            }
            TC_COMMIT(buf ? MB1 : MB0);
        }
    }

    MBAR_WAIT(MB0, ph0 & 1);
    MBAR_WAIT(MB1, ph1 & 1);
    TC_FENCE_AFTER();

    {
        const int half = wid >> 2, sub = wid & 3;
        const int row = bm + sub * 32 + lane;
#pragma unroll
        for (int cb = 0; cb < 2; cb++) {
            uint32_t col = (uint32_t)(half * 64 + cb * 32);
            uint32_t r[32];
            LDTM_X32(r, tmem + col);
            TC_WAIT_LD();
            float* Cp = C + (size_t)row * EMB + bn + col;
#pragma unroll
            for (int j = 0; j < 8; j++) {
                *(float4*)(Cp + j * 4) = make_float4(
                    __uint_as_float(r[4 * j + 0]), __uint_as_float(r[4 * j + 1]),
                    __uint_as_float(r[4 * j + 2]), __uint_as_float(r[4 * j + 3]));
            }
        }
        TC_FENCE_BEFORE();
    }
    __syncthreads();
    if (wid == 0) { TC_RELINQ(); TC_DEALLOC(tmem, 128); }

#else  // ---------------- SIMT fallback (non-sm_103a device binaries) ---------
    float* As = (float*)smem;
    float* Bs = (float*)smem + 8 * 128;
    const int tx = t & 15, ty = t >> 4;
    const int lrow = t >> 1, lk = (t & 1) << 2;
    const float* Ap = A + (size_t)(bm + lrow) * EMB + lk;
    const float* Wp = W + (size_t)(bn + lrow) * EMB + lk;

    float acc[8][8];
#pragma unroll
    for (int i = 0; i < 8; i++)
#pragma unroll
        for (int j = 0; j < 8; j++) acc[i][j] = 0.f;

    for (int k0 = 0; k0 < EMB; k0 += 8) {
        float4 av = *(const float4*)(Ap + k0);
        float4 wv = *(const float4*)(Wp + k0);
        __syncthreads();
        As[(lk+0)*128+lrow] = av.x; As[(lk+1)*128+lrow] = av.y;
        As[(lk+2)*128+lrow] = av.z; As[(lk+3)*128+lrow] = av.w;
        Bs[(lk+0)*128+lrow] = wv.x; Bs[(lk+1)*128+lrow] = wv.y;
        Bs[(lk+2)*128+lrow] = wv.z; Bs[(lk+3)*128+lrow] = wv.w;
        __syncthreads();
#pragma unroll
        for (int kk = 0; kk < 8; kk++) {
            float4 a0 = *(const float4*)&As[kk*128 + (ty << 2)];
            float4 a1 = *(const float4*)&As[kk*128 + 64 + (ty << 2)];
            float4 b0 = *(const float4*)&Bs[kk*128 + (tx << 2)];
            float4 b1 = *(const float4*)&Bs[kk*128 + 64 + (tx << 2)];
            float ar[8] = {a0.x,a0.y,a0.z,a0.w, a1.x,a1.y,a1.z,a1.w};
            float br[8] = {b0.x,b0.y,b0.z,b0.w, b1.x,b1.y,b1.z,b1.w};
#pragma unroll
            for (int i = 0; i < 8; i++)
#pragma unroll
                for (int j = 0; j < 8; j++)
                    acc[i][j] += ar[i] * br[j];
        }
    }
#pragma unroll
    for (int i = 0; i < 8; i++) {
        int r = bm + ((i < 4) ? ((ty << 2) + i) : (64 + (ty << 2) + i - 4));
        *(float4*)(C + (size_t)r * EMB + bn + (tx << 2)) =
            make_float4(acc[i][0], acc[i][1], acc[i][2], acc[i][3]);
        *(float4*)(C + (size_t)r * EMB + bn + 64 + (tx << 2)) =
            make_float4(acc[i][4], acc[i][5], acc[i][6], acc[i][7]);
    }
#endif
}

// ---------------------------------------------------------------------------
// Tensor-core flash attention, software-pipelined.
// K double-buffered; S(kt+1) issued back-to-back with PV(kt) so the tensor
// queue stays full; V/K loads overlap the in-flight S-MMA.
// ---------------------------------------------------------------------------
__global__ void __launch_bounds__(256, 1)
attention_kernel(const float* __restrict__ Qp, const float* __restrict__ Kp,
                 const float* __restrict__ Vp, float* __restrict__ O) {
    extern __shared__ __align__(1024) char smem[];
    const int t = threadIdx.x;
    const int qt = blockIdx.x, h = blockIdx.y, b = blockIdx.z;
    const size_t rowbase = (size_t)b * SEQ;

#if HAS_TCGEN05
    const uint32_t sb = smem_u32(smem);
    const int wid = t >> 5, lane = t & 31;
    const int sub = wid & 3, half = wid >> 2;
    const int row = sub * 32 + lane;          // q-row within tile (0..127)

    const uint32_t TMP = sb;                  // tmem ptr
    const uint32_t MBS = sb + 16;             // S-MMA barrier
    const uint32_t MBP = sb + 24;             // PV-MMA barrier
    float* halfmax = (float*)(smem + A_HMAX);
    float* halfsum = (float*)(smem + A_HSUM);

    if (t == 0) { MBAR_INIT(MBS, 1); MBAR_INIT(MBP, 1); }
    if (wid == 0) TC_ALLOC(TMP, 256);
    __syncthreads();
    uint32_t tmem;
    asm volatile("ld.shared.b32 %0, [%1];" : "=r"(tmem) : "r"(TMP));
    const uint32_t tm_s = tmem;               // S: cols 0-127
    const uint32_t tm_o = tmem + 128;         // O: cols 128-191

    const float* Qg = Qp + (rowbase + (size_t)qt * AQ) * EMB + h * HDIM;
    const float* Kg = Kp + rowbase * EMB + h * HDIM;
    const float* Vg = Vp + rowbase * EMB + h * HDIM;

    // ---- Load Q once: split bf16, K-major SW128 [128 rows][64 k] ----
    const float qscale = 0.125f * 1.44269504088896340736f;
#pragma unroll
    for (int it = 0; it < 8; it++) {
        int idx = it * 256 + t;
        int r = idx >> 4, g4 = idx & 15;
        float4 qv = *(const float4*)(Qg + (size_t)r * EMB + g4 * 4);
        float qf[4] = {qv.x * qscale, qv.y * qscale, qv.z * qscale, qv.w * qscale};
        __nv_bfloat16 qh4[4], ql4[4];
#pragma unroll
        for (int u = 0; u < 4; u++) {
            qh4[u] = __float2bfloat16(qf[u]);
            ql4[u] = __float2bfloat16(qf[u] - __bfloat162float(qh4[u]));
        }
        uint32_t off = r * 128 + g4 * 8;
        uint32_t sw  = off ^ ((off >> 3) & 0x70);
        *(uint2*)(smem + A_QH + sw) = make_uint2(pk2(qh4[0], qh4[1]), pk2(qh4[2], qh4[3]));
        *(uint2*)(smem + A_QL + sw) = make_uint2(pk2(ql4[0], ql4[1]), pk2(ql4[2], ql4[3]));
    }

    // ---- Prologue: load K(0) into stage 0, issue S(0) ----
#pragma unroll
    for (int it = 0; it < 8; it++) {
        int idx = it * 256 + t;
        int key = idx >> 4, g4 = idx & 15;
        float4 kv = *(const float4*)(Kg + (size_t)key * EMB + g4 * 4);
        float kf[4] = {kv.x, kv.y, kv.z, kv.w};
        __nv_bfloat16 kh4[4], kl4[4];
#pragma unroll
        for (int u = 0; u < 4; u++) {
            kh4[u] = __float2bfloat16(kf[u]);
            kl4[u] = __float2bfloat16(kf[u] - __bfloat162float(kh4[u]));
        }
        uint32_t off = key * 128 + g4 * 8;
        uint32_t sw  = off ^ ((off >> 3) & 0x70);
        *(uint2*)(smem + A_K0 + sw)         = make_uint2(pk2(kh4[0], kh4[1]), pk2(kh4[2], kh4[3]));
        *(uint2*)(smem + A_K0 + 16384 + sw) = make_uint2(pk2(kl4[0], kl4[1]), pk2(kl4[2], kl4[3]));
    }
    FENCE_PROXY();
    __syncthreads();

    const uint64_t dQh = mkdesc(sb + A_QH);
    const uint64_t dQl = mkdesc(sb + A_QL);
    const uint64_t dKh[2] = { mkdesc(sb + A_K0),         mkdesc(sb + A_K1) };
    const uint64_t dKl[2] = { mkdesc(sb + A_K0 + 16384), mkdesc(sb + A_K1 + 16384) };
    const uint64_t dVh = mkdesc(sb + A_VTH);
    const uint64_t dVl = mkdesc(sb + A_VTL);
    const uint64_t dPh = mkdesc(sb + A_PH);
    const uint64_t dPl = mkdesc(sb + A_PL);

    if (wid == 0 && elect_one()) {
        TC_FENCE_AFTER();
#pragma unroll
        for (int ks = 0; ks < 4; ks++) {
            mma_f16_ss(tm_s, dQh + ks * 2, dKh[0] + ks * 2, GIDESC, ks != 0);
            mma_f16_ss(tm_s, dQh + ks * 2, dKl[0] + ks * 2, GIDESC, 1u);
            mma_f16_ss(tm_s, dQl + ks * 2, dKh[0] + ks * 2, GIDESC, 1u);
        }
        TC_COMMIT(MBS);
    }

    float m = -__int_as_float(0x7f800000);    // -inf
    float l = 0.f;
    float o_acc[32];
#pragma unroll
    for (int j = 0; j < 32; j++) o_acc[j] = 0.f;

    for (int kt = 0; kt < NT; kt++) {
        // ---- overlap with in-flight S(kt): load V(kt) and K(kt+1) ----
        // V(kt): single buffer — PV(kt-1) completed at end of prior iter.
#pragma unroll
        for (int it = 0; it < 8; it++) {
            int idx = it * 256 + t;
            int key = idx >> 4, g4 = idx & 15;
            float4 vv = *(const float4*)(Vg + (size_t)(kt * AK + key) * EMB + g4 * 4);
            float vf[4] = {vv.x, vv.y, vv.z, vv.w};
#pragma unroll
            for (int u = 0; u < 4; u++) {
                int d = g4 * 4 + u;
                uint32_t voff = (key >> 6) * 8192 + (d >> 3) * 1024 + (d & 7) * 128 + (key & 63) * 2;
                uint32_t vsw  = voff ^ ((voff >> 3) & 0x70);
                __nv_bfloat16 vh = __float2bfloat16(vf[u]);
                __nv_bfloat16 vl = __float2bfloat16(vf[u] - __bfloat162float(vh));
                *(__nv_bfloat16*)(smem + A_VTH + vsw) = vh;
                *(__nv_bfloat16*)(smem + A_VTL + vsw) = vl;
            }
        }
        if (kt + 1 < NT) {
            const uint32_t kst = ((kt + 1) & 1) ? A_K1 : A_K0;
#pragma unroll
            for (int it = 0; it < 8; it++) {
                int idx = it * 256 + t;
                int key = idx >> 4, g4 = idx & 15;
                float4 kv = *(const float4*)(Kg + (size_t)((kt + 1) * AK + key) * EMB + g4 * 4);
                float kf[4] = {kv.x, kv.y, kv.z, kv.w};
                __nv_bfloat16 kh4[4], kl4[4];
#pragma unroll
                for (int u = 0; u < 4; u++) {
                    kh4[u] = __float2bfloat16(kf[u]);
                    kl4[u] = __float2bfloat16(kf[u] - __bfloat162float(kh4[u]));
                }
                uint32_t off = key * 128 + g4 * 8;
                uint32_t sw  = off ^ ((off >> 3) & 0x70);
                *(uint2*)(smem + kst + sw)         = make_uint2(pk2(kh4[0], kh4[1]), pk2(kh4[2], kh4[3]));
                *(uint2*)(smem + kst + 16384 + sw) = make_uint2(pk2(kl4[0], kl4[1]), pk2(kl4[2], kl4[3]));
            }
        }

        // ---- wait S(kt), read S ----
        MBAR_WAIT(MBS, kt & 1);
        TC_FENCE_AFTER();
        uint32_t s0[32], s1[32];
        LDTM_X32(s0, tm_s + half * 64);
        LDTM_X32(s1, tm_s + half * 64 + 32);
        TC_WAIT_LD();
        TC_FENCE_BEFORE();

        // ---- online softmax (base-2); lane owns one q-row ----
        float lmax = -__int_as_float(0x7f800000);
#pragma unroll
        for (int j = 0; j < 32; j++) {
            lmax = fmaxf(lmax, __uint_as_float(s0[j]));
            lmax = fmaxf(lmax, __uint_as_float(s1[j]));
        }
        halfmax[half * 128 + row] = lmax;
        __syncthreads();
        float mtile = fmaxf(lmax, halfmax[(half ^ 1) * 128 + row]);
        float mnew  = fmaxf(m, mtile);
        float corr  = ex2f(m - mnew);
        float psum  = 0.f;
        float p0[32], p1[32];
#pragma unroll
        for (int j = 0; j < 32; j++) {
            p0[j] = ex2f(__uint_as_float(s0[j]) - mnew);
            p1[j] = ex2f(__uint_as_float(s1[j]) - mnew);
            psum += p0[j] + p1[j];
        }
        halfsum[half * 128 + row] = psum;
        // ---- store P (split) to blocked smem ----
        {
            uint32_t base = (uint32_t)half * 16384 + (row >> 3) * 1024 + (row & 7) * 128;
#pragma unroll
            for (int j = 0; j < 16; j++) {
                __nv_bfloat16 h0 = __float2bfloat16(p0[2*j]);
                __nv_bfloat16 h1 = __float2bfloat16(p0[2*j+1]);
                __nv_bfloat16 h2 = __float2bfloat16(p1[2*j]);
                __nv_bfloat16 h3 = __float2bfloat16(p1[2*j+1]);
                __nv_bfloat16 l0 = __float2bfloat16(p0[2*j]   - __bfloat162float(h0));
                __nv_bfloat16 l1 = __float2bfloat16(p0[2*j+1] - __bfloat162float(h1));
                __nv_bfloat16 l2 = __float2bfloat16(p1[2*j]   - __bfloat162float(h2));
                __nv_bfloat16 l3 = __float2bfloat16(p1[2*j+1] - __bfloat162float(h3));
                uint32_t off  = base + j * 4;
                uint32_t sw   = off  ^ ((off  >> 3) & 0x70);
                uint32_t off2 = base + 64 + j * 4;
                uint32_t sw2  = off2 ^ ((off2 >> 3) & 0x70);
                *(uint32_t*)(smem + A_PH + sw)  = pk2(h0, h1);
                *(uint32_t*)(smem + A_PL + sw)  = pk2(l0, l1);
                *(uint32_t*)(smem + A_PH + sw2) = pk2(h2, h3);
                *(uint32_t*)(smem + A_PL + sw2) = pk2(l2, l3);
            }
        }
        FENCE_PROXY();
        __syncthreads();   // P + V(kt) + K(kt+1) + halfsum all visible

        l = l * corr + halfsum[0 * 128 + row] + halfsum[1 * 128 + row];
        m = mnew;
#pragma unroll
        for (int j = 0; j < 32; j++) o_acc[j] *= corr;

        // ---- issue PV(kt) and S(kt+1) back-to-back ----
        if (wid == 0 && elect_one()) {
            TC_FENCE_AFTER();
#pragma unroll
            for (int ks = 0; ks < 8; ks++) {
                uint64_t po = (uint64_t)((ks >> 2) * 1024 + (ks & 3) * 2);
                uint64_t vo = (uint64_t)((ks >> 2) * 512  + (ks & 3) * 2);
                mma_f16_ss(tm_o, dPh + po, dVh + vo, IDESC_PV, ks != 0);
                mma_f16_ss(tm_o, dPh + po, dVl + vo, IDESC_PV, 1u);
                mma_f16_ss(tm_o, dPl + po, dVh + vo, IDESC_PV, 1u);
            }
            TC_COMMIT(MBP);
            if (kt + 1 < NT) {
                const int nb = (kt + 1) & 1;
#pragma unroll
                for (int ks = 0; ks < 4; ks++) {
                    mma_f16_ss(tm_s, dQh + ks * 2, dKh[nb] + ks * 2, GIDESC, ks != 0);
                    mma_f16_ss(tm_s, dQh + ks * 2, dKl[nb] + ks * 2, GIDESC, 1u);
                    mma_f16_ss(tm_s, dQl + ks * 2, dKh[nb] + ks * 2, GIDESC, 1u);
                }
                TC_COMMIT(MBS);
            }
        }

        // ---- wait PV(kt), accumulate ----
        MBAR_WAIT(MBP, kt & 1);
        TC_FENCE_AFTER();
        {
            uint32_t r[32];
            LDTM_X32(r, tm_o + half * 32);
            TC_WAIT_LD();
#pragma unroll
            for (int j = 0; j < 32; j++) o_acc[j] += __uint_as_float(r[j]);
        }
        TC_FENCE_BEFORE();
    }

    // ---- epilogue ----
    {
        float inv = 1.0f / l;
        float* Op = O + (rowbase + (size_t)qt * AQ + row) * EMB + h * HDIM + half * 32;
#pragma unroll
        for (int j = 0; j < 8; j++)
            *(float4*)(Op + j * 4) = make_float4(o_acc[4*j] * inv, o_acc[4*j+1] * inv,
                                                 o_acc[4*j+2] * inv, o_acc[4*j+3] * inv);
    }
    __syncthreads();
    if (wid == 0) { TC_RELINQ(); TC_DEALLOC(tmem, 256); }

#else  // ---------------- SIMT fallback attention (non-sm_103a) ---------------
    float* sm = (float*)smem;
    float (*Qts)[128]  = (float (*)[128])sm;
    float (*Vs)[64]    = (float (*)[64])(sm + 64*128);
    float (*Kts)[64]   = (float (*)[64])(sm + 64*128 + 64*64);
    float (*Pts)[128]  = (float (*)[128])(sm + 64*128 + 64*64);

    const int tx = t & 15, ty = t >> 4;
    const float* Qg = Qp + (rowbase + (size_t)qt * 128) * EMB + h * HDIM;
    const float* Kg = Kp + rowbase * EMB + h * HDIM;
    const float* Vg = Vp + rowbase * EMB + h * HDIM;

    const float qscale = 0.125f * 1.44269504088896340736f;
#pragma unroll
    for (int it = 0; it < 8; it++) {
        int idx  = it * 256 + t;
        int qrow = idx >> 4, cg = idx & 15;
        float4 qv = *(const float4*)(Qg + (size_t)qrow * EMB + (cg << 2));
        float qf[4] = {qv.x, qv.y, qv.z, qv.w};
        int col = (((qrow >> 2) ^ cg) << 2) | (qrow & 3);
#pragma unroll
        for (int u = 0; u < 4; u++) Qts[(cg << 2) + u][col] = qscale * qf[u];
    }

    float m[8], l[8], acc[8][4];
#pragma unroll
    for (int i = 0; i < 8; i++) {
        m[i] = -__int_as_float(0x7f800000); l[i] = 0.f;
#pragma unroll
        for (int dd = 0; dd < 4; dd++) acc[i][dd] = 0.f;
    }

    for (int kt = 0; kt < SEQ / 64; kt++) {
        __syncthreads();
#pragma unroll
        for (int it = 0; it < 4; it++) {
            int idx = it * 256 + t;
            int key = idx >> 4, cg = idx & 15;
            float4 kv = *(const float4*)(Kg + (size_t)(kt * 64 + key) * EMB + (cg << 2));
            float kf[4] = {kv.x, kv.y, kv.z, kv.w};
            int col = (((key >> 2) ^ cg) << 2) | (key & 3);
#pragma unroll
            for (int u = 0; u < 4; u++) Kts[(cg << 2) + u][col] = kf[u];
            *(float4*)&Vs[key][cg << 2] =
                *(const float4*)(Vg + (size_t)(kt * 64 + key) * EMB + (cg << 2));
        }
        __syncthreads();

        float s_[8][4];
#pragma unroll
        for (int i = 0; i < 8; i++)
#pragma unroll
            for (int j = 0; j < 4; j++) s_[i][j] = 0.f;
#pragma unroll 8
        for (int d = 0; d < HDIM; d++) {
            int sw = (d >> 2) & 15;
            float4 k4 = *(const float4*)&Kts[d][(tx ^ sw) << 2];
            float4 q0 = *(const float4*)&Qts[d][((2 * ty) ^ sw) << 2];
            float4 q1 = *(const float4*)&Qts[d][((2 * ty + 1) ^ sw) << 2];
            float kf[4]  = {k4.x, k4.y, k4.z, k4.w};
            float q0f[4] = {q0.x, q0.y, q0.z, q0.w};
            float q1f[4] = {q1.x, q1.y, q1.z, q1.w};
#pragma unroll
            for (int i = 0; i < 4; i++)
#pragma unroll
                for (int j = 0; j < 4; j++) {
                    s_[i][j]     += q0f[i] * kf[j];
                    s_[4 + i][j] += q1f[i] * kf[j];
                }
        }

#pragma unroll
        for (int i = 0; i < 8; i++) {
            float mloc = fmaxf(fmaxf(s_[i][0], s_[i][1]), fmaxf(s_[i][2], s_[i][3]));
#pragma unroll
            for (int off = 8; off > 0; off >>= 1)
                mloc = fmaxf(mloc, __shfl_xor_sync(0xffffffffu, mloc, off, 16));
            float mnew = fmaxf(m[i], mloc);
            float corr = ex2f(m[i] - mnew);
            float rsum = 0.f;
#pragma unroll
            for (int j = 0; j < 4; j++) {
                float pv = ex2f(s_[i][j] - mnew);
                s_[i][j] = pv; rsum += pv;
            }
#pragma unroll
            for (int off = 8; off > 0; off >>= 1)
                rsum += __shfl_xor_sync(0xffffffffu, rsum, off, 16);
            l[i] = l[i] * corr + rsum; m[i] = mnew;
#pragma unroll
            for (int dd = 0; dd < 4; dd++) acc[i][dd] *= corr;
        }

        __syncthreads();
#pragma unroll
        for (int j = 0; j < 4; j++) {
            int key = (tx << 2) + j;
            int swp = key & 31;
            *(float4*)&Pts[key][((2 * ty) ^ swp) << 2] =
                make_float4(s_[0][j], s_[1][j], s_[2][j], s_[3][j]);
            *(float4*)&Pts[key][((2 * ty + 1) ^ swp) << 2] =
                make_float4(s_[4][j], s_[5][j], s_[6][j], s_[7][j]);
        }
        __syncthreads();

#pragma unroll 8
        for (int j = 0; j < 64; j++) {
            int swp = j & 31;
            float4 pp0 = *(const float4*)&Pts[j][((2 * ty) ^ swp) << 2];
            float4 pp1 = *(const float4*)&Pts[j][((2 * ty + 1) ^ swp) << 2];
            float4 v4 = *(const float4*)&Vs[j][tx << 2];
            float pf[8] = {pp0.x,pp0.y,pp0.z,pp0.w, pp1.x,pp1.y,pp1.z,pp1.w};
            float vf[4] = {v4.x, v4.y, v4.z, v4.w};
#pragma unroll
            for (int i = 0; i < 8; i++)
#pragma unroll
                for (int dd = 0; dd < 4; dd++)
                    acc[i][dd] += pf[i] * vf[dd];
        }
    }

#pragma unroll
    for (int i = 0; i < 8; i++) {
        float inv = 1.0f / l[i];
        int r = qt * 128 + (ty << 3) + i;
        *(float4*)(O + (rowbase + r) * EMB + h * HDIM + (tx << 2)) =
            make_float4(acc[i][0]*inv, acc[i][1]*inv, acc[i][2]*inv, acc[i][3]*inv);
    }
#endif
}

// ---------------------------------------------------------------------------
extern "C" void kernel_launch(void* const* d_in, const int* in_sizes, int n_in,
                              void* d_out, int out_size) {
    const float* query = (const float*)d_in[0];
    const float* key   = (const float*)d_in[1];
    const float* value = (const float*)d_in[2];
    const float* Wq    = (const float*)d_in[3];
    const float* Wk    = (const float*)d_in[4];
    const float* Wv    = (const float*)d_in[5];
    const float* Wo    = (const float*)d_in[6];
    float* out = (float*)d_out;

    float *q, *k, *v, *ctx;
    cudaGetSymbolAddress((void**)&q,   g_q);
    cudaGetSymbolAddress((void**)&k,   g_k);
    cudaGetSymbolAddress((void**)&v,   g_v);
    cudaGetSymbolAddress((void**)&ctx, g_ctx);

    cudaFuncSetAttribute(gemm_tc_kernel,
                         cudaFuncAttributeMaxDynamicSharedMemorySize, GSMEM);
    cudaFuncSetAttribute(attention_kernel,
                         cudaFuncAttributeMaxDynamicSharedMemorySize, ASMEM);

    dim3 gg(EMB / 128, MTOT / 128);
    gemm_tc_kernel<<<gg, 256, GSMEM>>>(query, Wq, q);
    gemm_tc_kernel<<<gg, 256, GSMEM>>>(key,   Wk, k);
    gemm_tc_kernel<<<gg, 256, GSMEM>>>(value, Wv, v);
    attention_kernel<<<dim3(SEQ / AQ, NHEAD, BATCH), 256, ASMEM>>>(q, k, v, ctx);
    gemm_tc_kernel<<<gg, 256, GSMEM>>>(ctx, Wo, out);
}

// round 13
// speedup vs baseline: 1.0990x; 1.0990x over previous
#include <cuda_runtime.h>
#include <cuda_bf16.h>
#include <cstdint>

#define EMB   1024
#define NHEAD 16
#define HDIM  64
#define BATCH 4
#define SEQ   2048
#define MTOT  (BATCH*SEQ)

// GEMM tensor-core config
#define GKC        64                 // K elements per chunk (64 bf16 = 128B = SW128 row)
#define TILE_B     16384              // one 128x64 bf16 tile
#define STAGE_B    (4*TILE_B)         // Ah, Al, Bh, Bl
#define GSMEM      (1024 + 2*STAGE_B) // 132096 bytes

// Attention config
#define AQ 128            // q rows per CTA
#define AK 128            // keys per tile
#define NT (SEQ/AK)       // 16 tiles
// attention smem offsets (bytes). K double-buffered, V single, P single.
#define A_HMAX    64       // float[2][128]
#define A_HSUM    1088     // float[2][128]
#define A_QH      3072
#define A_QL      (A_QH  + 16384)
#define A_K0      (A_QL  + 16384)    // stage0: KH, KL
#define A_K1      (A_K0  + 32768)    // stage1: KH, KL
#define A_VTH     (A_K1  + 32768)    // V transposed blocked [key-blk][d-grp][d&7][key&63] hi
#define A_VTL     (A_VTH + 16384)    // V lo
#define A_PH      (A_VTL + 16384)
#define A_PL      (A_PH  + 32768)
#define ASMEM     (A_PL  + 32768)    // 199680

// Scratch (device-global: allocation-guard-safe)
__device__ float g_q[MTOT*EMB];
__device__ float g_k[MTOT*EMB];
__device__ float g_v[MTOT*EMB];
__device__ float g_ctx[MTOT*EMB];

__device__ __forceinline__ float ex2f(float x) {
    float y; asm("ex2.approx.ftz.f32 %0, %1;" : "=f"(y) : "f"(x)); return y;
}

// HAS_TCGEN05 is 1 in the host pass (parses, never assembles) and in the
// compute_103a device pass. It is 0 ONLY in non-feature device passes
// (e.g. compute_103), which must never see tcgen05 asm (ptxas rejects it).
#if defined(__CUDA_ARCH_FEAT_SM103_ALL) || !defined(__CUDA_ARCH__)
#define HAS_TCGEN05 1
#else
#define HAS_TCGEN05 0
#endif

#if HAS_TCGEN05
// ---------------- tcgen05 helpers (parsed on host; emitted only on sm_103a) ----
__device__ __forceinline__ uint32_t elect_one() {
    uint32_t pr;
    asm volatile("{\n\t.reg .pred p;\n\telect.sync _|p, 0xFFFFFFFF;\n\t"
                 "selp.b32 %0, 1, 0, p;\n\t}" : "=r"(pr));
    return pr;
}
__device__ __forceinline__ uint64_t mkdesc(uint32_t addr) {  // SW128 K-major, LBO=1, SBO=64
    const uint64_t base = (uint64_t(2) << 61) | (uint64_t(1) << 46)
                        | (uint64_t(64) << 32) | (uint64_t(1) << 16);
    return base | ((uint64_t)(addr >> 4) & 0x3FFF);
}
__device__ __forceinline__ void mma_f16_ss(uint32_t d, uint64_t ad, uint64_t bd,
                                           uint32_t idesc, uint32_t en) {
    asm volatile("{\n\t.reg .pred p;\n\tsetp.ne.u32 p, %5, 0;\n\t"
        "tcgen05.mma.cta_group::1.kind::f16 [%0], %1, %2, %3, {%4,%4,%4,%4}, p;\n\t}"
        :: "r"(d), "l"(ad), "l"(bd), "r"(idesc), "r"(0u), "r"(en) : "memory");
}
#define TC_COMMIT(a) \
    asm volatile("tcgen05.commit.cta_group::1.mbarrier::arrive::one.shared::cluster.b64 [%0];" \
                 :: "r"(a) : "memory")
#define TC_ALLOC(sres, n) \
    asm volatile("tcgen05.alloc.cta_group::1.sync.aligned.shared::cta.b32 [%0], %1;" \
                 :: "r"(sres), "r"((uint32_t)(n)) : "memory")
#define TC_DEALLOC(tm, n) \
    asm volatile("tcgen05.dealloc.cta_group::1.sync.aligned.b32 %0, %1;" :: "r"(tm), "r"((uint32_t)(n)))
#define TC_RELINQ() asm volatile("tcgen05.relinquish_alloc_permit.cta_group::1.sync.aligned;")
#define TC_FENCE_AFTER()  asm volatile("tcgen05.fence::after_thread_sync;" ::: "memory")
#define TC_FENCE_BEFORE() asm volatile("tcgen05.fence::before_thread_sync;" ::: "memory")
#define TC_WAIT_LD() asm volatile("tcgen05.wait::ld.sync.aligned;" ::: "memory")
#define LDTM_X32(r, a) \
    asm volatile("tcgen05.ld.sync.aligned.32x32b.x32.b32 "                        \
        "{%0,%1,%2,%3,%4,%5,%6,%7,%8,%9,%10,%11,%12,%13,%14,%15,"                 \
        "%16,%17,%18,%19,%20,%21,%22,%23,%24,%25,%26,%27,%28,%29,%30,%31}, [%32];"\
        : "=r"((r)[0]),"=r"((r)[1]),"=r"((r)[2]),"=r"((r)[3]),                    \
          "=r"((r)[4]),"=r"((r)[5]),"=r"((r)[6]),"=r"((r)[7]),                    \
          "=r"((r)[8]),"=r"((r)[9]),"=r"((r)[10]),"=r"((r)[11]),                  \
          "=r"((r)[12]),"=r"((r)[13]),"=r"((r)[14]),"=r"((r)[15]),                \
          "=r"((r)[16]),"=r"((r)[17]),"=r"((r)[18]),"=r"((r)[19]),                \
          "=r"((r)[20]),"=r"((r)[21]),"=r"((r)[22]),"=r"((r)[23]),                \
          "=r"((r)[24]),"=r"((r)[25]),"=r"((r)[26]),"=r"((r)[27]),                \
          "=r"((r)[28]),"=r"((r)[29]),"=r"((r)[30]),"=r"((r)[31])                 \
        : "r"(a))
#endif // HAS_TCGEN05 helpers

// ---- arch-independent helpers ----
__device__ __forceinline__ uint32_t smem_u32(const void* p) {
    uint32_t a;
    asm("{ .reg .u64 t; cvta.to.shared.u64 t, %1; cvt.u32.u64 %0, t; }"
        : "=r"(a) : "l"(p));
    return a;
}
#define MBAR_INIT(a, n) \
    asm volatile("mbarrier.init.shared.b64 [%0], %1;" :: "r"(a), "r"(n) : "memory")
#define MBAR_WAIT(a, par) do {                                                    \
    uint32_t _m = (a), _p = (par), _d;                                            \
    asm volatile("{\n\t.reg .pred p;\n\t"                                         \
        "mbarrier.try_wait.parity.acquire.cta.shared::cta.b64 p, [%1], %2;\n\t"   \
        "selp.b32 %0, 1, 0, p;\n\t}" : "=r"(_d) : "r"(_m), "r"(_p) : "memory");   \
    if (!_d) {                                                                    \
        asm volatile("{\n\t.reg .pred P1;\n\tWL_%=:\n\t"                          \
            "mbarrier.try_wait.parity.acquire.cta.shared::cta.b64 P1, [%0], %1, 0x989680;\n\t" \
            "@P1 bra.uni WD_%=;\n\tbra.uni WL_%=;\n\tWD_%=:\n\t}"                 \
            :: "r"(_m), "r"(_p) : "memory");                                      \
    } } while (0)
#define FENCE_PROXY() asm volatile("fence.proxy.async.shared::cta;" ::: "memory")

__device__ __forceinline__ uint32_t pk2(__nv_bfloat16 lo, __nv_bfloat16 hi) {
    return (uint32_t)__bfloat16_as_ushort(lo) | ((uint32_t)__bfloat16_as_ushort(hi) << 16);
}

// idescs: F32 acc, BF16 a/b, M=128 (both K-major — validated forms only)
#define GIDESC   ((1u<<4)|(1u<<7)|(1u<<10)|((128u/8)<<17)|((128u/16)<<24))  // N=128
#define IDESC_PV ((1u<<4)|(1u<<7)|(1u<<10)|(( 64u/8)<<17)|((128u/16)<<24))  // N=64

// ---------------------------------------------------------------------------
// C[M,N] = A[M,K] * W[N,K]^T  (unchanged — validated tcgen05 path)
// ---------------------------------------------------------------------------
__global__ void __launch_bounds__(256, 1)
gemm_tc_kernel(const float* __restrict__ A, const float* __restrict__ W,
               float* __restrict__ C) {
    extern __shared__ __align__(1024) char smem[];
    const int t = threadIdx.x;
    const int bm = blockIdx.y << 7, bn = blockIdx.x << 7;

#if HAS_TCGEN05
    const uint32_t sb = smem_u32(smem);
    const int wid = t >> 5, lane = t & 31;
    const uint32_t TMP   = sb;
    const uint32_t MB0   = sb + 16;
    const uint32_t MB1   = sb + 24;
    const uint32_t TILES = sb + 1024;

    if (t == 0) { MBAR_INIT(MB0, 1); MBAR_INIT(MB1, 1); }
    if (wid == 0) TC_ALLOC(TMP, 128);
    __syncthreads();
    uint32_t tmem;
    asm volatile("ld.shared.b32 %0, [%1];" : "=r"(tmem) : "r"(TMP));

    int ph0 = 0, ph1 = 0;

    for (int c = 0; c < EMB / GKC; c++) {
        const int buf = c & 1;
        if (c >= 2) {
            if (buf == 0) { MBAR_WAIT(MB0, ph0 & 1); ph0++; }
            else          { MBAR_WAIT(MB1, ph1 & 1); ph1++; }
        }
        const uint32_t stage = TILES + buf * STAGE_B;
#pragma unroll
        for (int it = 0; it < 8; it++) {
            int idx = it * 256 + t;
            int row = idx >> 4, g4 = idx & 15;
            float4 av = *(const float4*)(A + (size_t)(bm + row) * EMB + c * GKC + g4 * 4);
            float4 wv = *(const float4*)(W + (size_t)(bn + row) * EMB + c * GKC + g4 * 4);
            uint32_t off = row * 128 + g4 * 8;
            uint32_t sw  = off ^ ((off >> 3) & 0x70);
            float af[4] = {av.x, av.y, av.z, av.w};
            float wf[4] = {wv.x, wv.y, wv.z, wv.w};
            __nv_bfloat16 ah[4], al[4], wh[4], wl[4];
#pragma unroll
            for (int u = 0; u < 4; u++) {
                ah[u] = __float2bfloat16(af[u]);
                al[u] = __float2bfloat16(af[u] - __bfloat162float(ah[u]));
                wh[u] = __float2bfloat16(wf[u]);
                wl[u] = __float2bfloat16(wf[u] - __bfloat162float(wh[u]));
            }
            char* stp = smem + (stage - sb);
            *(uint2*)(stp + 0 * TILE_B + sw) = make_uint2(pk2(ah[0], ah[1]), pk2(ah[2], ah[3]));
            *(uint2*)(stp + 1 * TILE_B + sw) = make_uint2(pk2(al[0], al[1]), pk2(al[2], al[3]));
            *(uint2*)(stp + 2 * TILE_B + sw) = make_uint2(pk2(wh[0], wh[1]), pk2(wh[2], wh[3]));
            *(uint2*)(stp + 3 * TILE_B + sw) = make_uint2(pk2(wl[0], wl[1]), pk2(wl[2], wl[3]));
        }
        FENCE_PROXY();
        __syncthreads();

        if (wid == 0 && elect_one()) {
            uint64_t dAh = mkdesc(stage + 0 * TILE_B);
            uint64_t dAl = mkdesc(stage + 1 * TILE_B);
            uint64_t dBh = mkdesc(stage + 2 * TILE_B);
            uint64_t dBl = mkdesc(stage + 3 * TILE_B);
#pragma unroll
            for (int ks = 0; ks < 4; ks++) {
                uint32_t en0 = !(c == 0 && ks == 0);
                mma_f16_ss(tmem, dAh + ks * 2, dBh + ks * 2, GIDESC, en0);
                mma_f16_ss(tmem, dAh + ks * 2, dBl + ks * 2, GIDESC, 1u);
                mma_f16_ss(tmem, dAl + ks * 2, dBh + ks * 2, GIDESC, 1u);
            }
            TC_COMMIT(buf ? MB1 : MB0);
        }
    }

    MBAR_WAIT(MB0, ph0 & 1);
    MBAR_WAIT(MB1, ph1 & 1);
    TC_FENCE_AFTER();

    {
        const int half = wid >> 2, sub = wid & 3;
        const int row = bm + sub * 32 + lane;
#pragma unroll
        for (int cb = 0; cb < 2; cb++) {
            uint32_t col = (uint32_t)(half * 64 + cb * 32);
            uint32_t r[32];
            LDTM_X32(r, tmem + col);
            TC_WAIT_LD();
            float* Cp = C + (size_t)row * EMB + bn + col;
#pragma unroll
            for (int j = 0; j < 8; j++) {
                *(float4*)(Cp + j * 4) = make_float4(
                    __uint_as_float(r[4 * j + 0]), __uint_as_float(r[4 * j + 1]),
                    __uint_as_float(r[4 * j + 2]), __uint_as_float(r[4 * j + 3]));
            }
        }
        TC_FENCE_BEFORE();
    }
    __syncthreads();
    if (wid == 0) { TC_RELINQ(); TC_DEALLOC(tmem, 128); }

#else  // ---------------- SIMT fallback (non-sm_103a device binaries) ---------
    float* As = (float*)smem;
    float* Bs = (float*)smem + 8 * 128;
    const int tx = t & 15, ty = t >> 4;
    const int lrow = t >> 1, lk = (t & 1) << 2;
    const float* Ap = A + (size_t)(bm + lrow) * EMB + lk;
    const float* Wp = W + (size_t)(bn + lrow) * EMB + lk;

    float acc[8][8];
#pragma unroll
    for (int i = 0; i < 8; i++)
#pragma unroll
        for (int j = 0; j < 8; j++) acc[i][j] = 0.f;

    for (int k0 = 0; k0 < EMB; k0 += 8) {
        float4 av = *(const float4*)(Ap + k0);
        float4 wv = *(const float4*)(Wp + k0);
        __syncthreads();
        As[(lk+0)*128+lrow] = av.x; As[(lk+1)*128+lrow] = av.y;
        As[(lk+2)*128+lrow] = av.z; As[(lk+3)*128+lrow] = av.w;
        Bs[(lk+0)*128+lrow] = wv.x; Bs[(lk+1)*128+lrow] = wv.y;
        Bs[(lk+2)*128+lrow] = wv.z; Bs[(lk+3)*128+lrow] = wv.w;
        __syncthreads();
#pragma unroll
        for (int kk = 0; kk < 8; kk++) {
            float4 a0 = *(const float4*)&As[kk*128 + (ty << 2)];
            float4 a1 = *(const float4*)&As[kk*128 + 64 + (ty << 2)];
            float4 b0 = *(const float4*)&Bs[kk*128 + (tx << 2)];
            float4 b1 = *(const float4*)&Bs[kk*128 + 64 + (tx << 2)];
            float ar[8] = {a0.x,a0.y,a0.z,a0.w, a1.x,a1.y,a1.z,a1.w};
            float br[8] = {b0.x,b0.y,b0.z,b0.w, b1.x,b1.y,b1.z,b1.w};
#pragma unroll
            for (int i = 0; i < 8; i++)
#pragma unroll
                for (int j = 0; j < 8; j++)
                    acc[i][j] += ar[i] * br[j];
        }
    }
#pragma unroll
    for (int i = 0; i < 8; i++) {
        int r = bm + ((i < 4) ? ((ty << 2) + i) : (64 + (ty << 2) + i - 4));
        *(float4*)(C + (size_t)r * EMB + bn + (tx << 2)) =
            make_float4(acc[i][0], acc[i][1], acc[i][2], acc[i][3]);
        *(float4*)(C + (size_t)r * EMB + bn + 64 + (tx << 2)) =
            make_float4(acc[i][4], acc[i][5], acc[i][6], acc[i][7]);
    }
#endif
}

// ---------------------------------------------------------------------------
// Tensor-core flash attention, software-pipelined.
// V transposed into the R7-validated blocked K-major layout, but with a
// conflict-free store assignment: thread owns (d = t>>2, keygroup = t&3) and
// writes 32 contiguous keys of row d as 8-byte stores (2-phase, no conflicts)
// instead of 64 scattered 2-byte stores (8-way conflicts).
// ---------------------------------------------------------------------------
__global__ void __launch_bounds__(256, 1)
attention_kernel(const float* __restrict__ Qp, const float* __restrict__ Kp,
                 const float* __restrict__ Vp, float* __restrict__ O) {
    extern __shared__ __align__(1024) char smem[];
    const int t = threadIdx.x;
    const int qt = blockIdx.x, h = blockIdx.y, b = blockIdx.z;
    const size_t rowbase = (size_t)b * SEQ;

#if HAS_TCGEN05
    const uint32_t sb = smem_u32(smem);
    const int wid = t >> 5, lane = t & 31;
    const int sub = wid & 3, half = wid >> 2;
    const int row = sub * 32 + lane;          // q-row within tile (0..127)

    const uint32_t TMP = sb;                  // tmem ptr
    const uint32_t MBS = sb + 16;             // S-MMA barrier
    const uint32_t MBP = sb + 24;             // PV-MMA barrier
    float* halfmax = (float*)(smem + A_HMAX);
    float* halfsum = (float*)(smem + A_HSUM);

    if (t == 0) { MBAR_INIT(MBS, 1); MBAR_INIT(MBP, 1); }
    if (wid == 0) TC_ALLOC(TMP, 256);
    __syncthreads();
    uint32_t tmem;
    asm volatile("ld.shared.b32 %0, [%1];" : "=r"(tmem) : "r"(TMP));
    const uint32_t tm_s = tmem;               // S: cols 0-127
    const uint32_t tm_o = tmem + 128;         // O: cols 128-191

    const float* Qg = Qp + (rowbase + (size_t)qt * AQ) * EMB + h * HDIM;
    const float* Kg = Kp + rowbase * EMB + h * HDIM;
    const float* Vg = Vp + rowbase * EMB + h * HDIM;

    // ---- Load Q once: split bf16, K-major SW128 [128 rows][64 k] ----
    const float qscale = 0.125f * 1.44269504088896340736f;
#pragma unroll
    for (int it = 0; it < 8; it++) {
        int idx = it * 256 + t;
        int r = idx >> 4, g4 = idx & 15;
        float4 qv = *(const float4*)(Qg + (size_t)r * EMB + g4 * 4);
        float qf[4] = {qv.x * qscale, qv.y * qscale, qv.z * qscale, qv.w * qscale};
        __nv_bfloat16 qh4[4], ql4[4];
#pragma unroll
        for (int u = 0; u < 4; u++) {
            qh4[u] = __float2bfloat16(qf[u]);
            ql4[u] = __float2bfloat16(qf[u] - __bfloat162float(qh4[u]));
        }
        uint32_t off = r * 128 + g4 * 8;
        uint32_t sw  = off ^ ((off >> 3) & 0x70);
        *(uint2*)(smem + A_QH + sw) = make_uint2(pk2(qh4[0], qh4[1]), pk2(qh4[2], qh4[3]));
        *(uint2*)(smem + A_QL + sw) = make_uint2(pk2(ql4[0], ql4[1]), pk2(ql4[2], ql4[3]));
    }

    // ---- Prologue: load K(0) into stage 0, issue S(0) ----
#pragma unroll
    for (int it = 0; it < 8; it++) {
        int idx = it * 256 + t;
        int key = idx >> 4, g4 = idx & 15;
        float4 kv = *(const float4*)(Kg + (size_t)key * EMB + g4 * 4);
        float kf[4] = {kv.x, kv.y, kv.z, kv.w};
        __nv_bfloat16 kh4[4], kl4[4];
#pragma unroll
        for (int u = 0; u < 4; u++) {
            kh4[u] = __float2bfloat16(kf[u]);
            kl4[u] = __float2bfloat16(kf[u] - __bfloat162float(kh4[u]));
        }
        uint32_t off = key * 128 + g4 * 8;
        uint32_t sw  = off ^ ((off >> 3) & 0x70);
        *(uint2*)(smem + A_K0 + sw)         = make_uint2(pk2(kh4[0], kh4[1]), pk2(kh4[2], kh4[3]));
        *(uint2*)(smem + A_K0 + 16384 + sw) = make_uint2(pk2(kl4[0], kl4[1]), pk2(kl4[2], kl4[3]));
    }
    FENCE_PROXY();
    __syncthreads();

    const uint64_t dQh = mkdesc(sb + A_QH);
    const uint64_t dQl = mkdesc(sb + A_QL);
    const uint64_t dKh[2] = { mkdesc(sb + A_K0),         mkdesc(sb + A_K1) };
    const uint64_t dKl[2] = { mkdesc(sb + A_K0 + 16384), mkdesc(sb + A_K1 + 16384) };
    const uint64_t dVh = mkdesc(sb + A_VTH);
    const uint64_t dVl = mkdesc(sb + A_VTL);
    const uint64_t dPh = mkdesc(sb + A_PH);
    const uint64_t dPl = mkdesc(sb + A_PL);

    if (wid == 0 && elect_one()) {
        TC_FENCE_AFTER();
#pragma unroll
        for (int ks = 0; ks < 4; ks++) {
            mma_f16_ss(tm_s, dQh + ks * 2, dKh[0] + ks * 2, GIDESC, ks != 0);
            mma_f16_ss(tm_s, dQh + ks * 2, dKl[0] + ks * 2, GIDESC, 1u);
            mma_f16_ss(tm_s, dQl + ks * 2, dKh[0] + ks * 2, GIDESC, 1u);
        }
        TC_COMMIT(MBS);
    }

    float m = -__int_as_float(0x7f800000);    // -inf
    float l = 0.f;
    float o_acc[32];
#pragma unroll
    for (int j = 0; j < 32; j++) o_acc[j] = 0.f;

    // V-store assignment: thread owns row d = t>>2, keys [kg*32, kg*32+32)
    const int vd = t >> 2, vkg = t & 3;
    const uint32_t vbase = (uint32_t)((vkg >> 1) * 8192 + (vd >> 3) * 1024
                                    + (vd & 7) * 128 + (vkg & 1) * 64);
    const float* VgT = Vg + vd;   // column vd

    for (int kt = 0; kt < NT; kt++) {
        // ---- overlap with in-flight S(kt): load V(kt) and K(kt+1) ----
        // V(kt): transposed blocked layout; 8-byte conflict-free stores.
#pragma unroll
        for (int j = 0; j < 8; j++) {
            const float* vp = VgT + (size_t)(kt * AK + vkg * 32 + 4 * j) * EMB;
            float f0 = vp[0];
            float f1 = vp[EMB];
            float f2 = vp[2 * EMB];
            float f3 = vp[3 * EMB];
            __nv_bfloat16 h0 = __float2bfloat16(f0);
            __nv_bfloat16 h1 = __float2bfloat16(f1);
            __nv_bfloat16 h2 = __float2bfloat16(f2);
            __nv_bfloat16 h3 = __float2bfloat16(f3);
            __nv_bfloat16 l0 = __float2bfloat16(f0 - __bfloat162float(h0));
            __nv_bfloat16 l1 = __float2bfloat16(f1 - __bfloat162float(h1));
            __nv_bfloat16 l2 = __float2bfloat16(f2 - __bfloat162float(h2));
            __nv_bfloat16 l3 = __float2bfloat16(f3 - __bfloat162float(h3));
            uint32_t off = vbase + j * 8;
            uint32_t sw  = off ^ ((off >> 3) & 0x70);
            *(uint2*)(smem + A_VTH + sw) = make_uint2(pk2(h0, h1), pk2(h2, h3));
            *(uint2*)(smem + A_VTL + sw) = make_uint2(pk2(l0, l1), pk2(l2, l3));
        }
        if (kt + 1 < NT) {
            const uint32_t kst = ((kt + 1) & 1) ? A_K1 : A_K0;
#pragma unroll
            for (int it = 0; it < 8; it++) {
                int idx = it * 256 + t;
                int key = idx >> 4, g4 = idx & 15;
                float4 kv = *(const float4*)(Kg + (size_t)((kt + 1) * AK + key) * EMB + g4 * 4);
                float kf[4] = {kv.x, kv.y, kv.z, kv.w};
                __nv_bfloat16 kh4[4], kl4[4];
#pragma unroll
                for (int u = 0; u < 4; u++) {
                    kh4[u] = __float2bfloat16(kf[u]);
                    kl4[u] = __float2bfloat16(kf[u] - __bfloat162float(kh4[u]));
                }
                uint32_t off = key * 128 + g4 * 8;
                uint32_t sw  = off ^ ((off >> 3) & 0x70);
                *(uint2*)(smem + kst + sw)         = make_uint2(pk2(kh4[0], kh4[1]), pk2(kh4[2], kh4[3]));
                *(uint2*)(smem + kst + 16384 + sw) = make_uint2(pk2(kl4[0], kl4[1]), pk2(kl4[2], kl4[3]));
            }
        }

        // ---- wait S(kt), read S ----
        MBAR_WAIT(MBS, kt & 1);
        TC_FENCE_AFTER();
        uint32_t s0[32], s1[32];
        LDTM_X32(s0, tm_s + half * 64);
        LDTM_X32(s1, tm_s + half * 64 + 32);
        TC_WAIT_LD();
        TC_FENCE_BEFORE();

        // ---- online softmax (base-2); lane owns one q-row ----
        float lmax = -__int_as_float(0x7f800000);
#pragma unroll
        for (int j = 0; j < 32; j++) {
            lmax = fmaxf(lmax, __uint_as_float(s0[j]));
            lmax = fmaxf(lmax, __uint_as_float(s1[j]));
        }
        halfmax[half * 128 + row] = lmax;
        __syncthreads();
        float mtile = fmaxf(lmax, halfmax[(half ^ 1) * 128 + row]);
        float mnew  = fmaxf(m, mtile);
        float corr  = ex2f(m - mnew);
        float psum  = 0.f;
        float p0[32], p1[32];
#pragma unroll
        for (int j = 0; j < 32; j++) {
            p0[j] = ex2f(__uint_as_float(s0[j]) - mnew);
            p1[j] = ex2f(__uint_as_float(s1[j]) - mnew);
            psum += p0[j] + p1[j];
        }
        halfsum[half * 128 + row] = psum;
        // ---- store P (split) to blocked smem ----
        {
            uint32_t base = (uint32_t)half * 16384 + (row >> 3) * 1024 + (row & 7) * 128;
#pragma unroll
            for (int j = 0; j < 16; j++) {
                __nv_bfloat16 h0 = __float2bfloat16(p0[2*j]);
                __nv_bfloat16 h1 = __float2bfloat16(p0[2*j+1]);
                __nv_bfloat16 h2 = __float2bfloat16(p1[2*j]);
                __nv_bfloat16 h3 = __float2bfloat16(p1[2*j+1]);
                __nv_bfloat16 l0 = __float2bfloat16(p0[2*j]   - __bfloat162float(h0));
                __nv_bfloat16 l1 = __float2bfloat16(p0[2*j+1] - __bfloat162float(h1));
                __nv_bfloat16 l2 = __float2bfloat16(p1[2*j]   - __bfloat162float(h2));
                __nv_bfloat16 l3 = __float2bfloat16(p1[2*j+1] - __bfloat162float(h3));
                uint32_t off  = base + j * 4;
                uint32_t sw   = off  ^ ((off  >> 3) & 0x70);
                uint32_t off2 = base + 64 + j * 4;
                uint32_t sw2  = off2 ^ ((off2 >> 3) & 0x70);
                *(uint32_t*)(smem + A_PH + sw)  = pk2(h0, h1);
                *(uint32_t*)(smem + A_PL + sw)  = pk2(l0, l1);
                *(uint32_t*)(smem + A_PH + sw2) = pk2(h2, h3);
                *(uint32_t*)(smem + A_PL + sw2) = pk2(l2, l3);
            }
        }
        FENCE_PROXY();
        __syncthreads();   // P + V(kt) + K(kt+1) + halfsum all visible

        l = l * corr + halfsum[0 * 128 + row] + halfsum[1 * 128 + row];
        m = mnew;
#pragma unroll
        for (int j = 0; j < 32; j++) o_acc[j] *= corr;

        // ---- issue PV(kt) and S(kt+1) back-to-back ----
        if (wid == 0 && elect_one()) {
            TC_FENCE_AFTER();
#pragma unroll
            for (int ks = 0; ks < 8; ks++) {
                uint64_t po = (uint64_t)((ks >> 2) * 1024 + (ks & 3) * 2);
                uint64_t vo = (uint64_t)((ks >> 2) * 512  + (ks & 3) * 2);
                mma_f16_ss(tm_o, dPh + po, dVh + vo, IDESC_PV, ks != 0);
                mma_f16_ss(tm_o, dPh + po, dVl + vo, IDESC_PV, 1u);
                mma_f16_ss(tm_o, dPl + po, dVh + vo, IDESC_PV, 1u);
            }
            TC_COMMIT(MBP);
            if (kt + 1 < NT) {
                const int nb = (kt + 1) & 1;
#pragma unroll
                for (int ks = 0; ks < 4; ks++) {
                    mma_f16_ss(tm_s, dQh + ks * 2, dKh[nb] + ks * 2, GIDESC, ks != 0);
                    mma_f16_ss(tm_s, dQh + ks * 2, dKl[nb] + ks * 2, GIDESC, 1u);
                    mma_f16_ss(tm_s, dQl + ks * 2, dKh[nb] + ks * 2, GIDESC, 1u);
                }
                TC_COMMIT(MBS);
            }
        }

        // ---- wait PV(kt), accumulate ----
        MBAR_WAIT(MBP, kt & 1);
        TC_FENCE_AFTER();
        {
            uint32_t r[32];
            LDTM_X32(r, tm_o + half * 32);
            TC_WAIT_LD();
#pragma unroll
            for (int j = 0; j < 32; j++) o_acc[j] += __uint_as_float(r[j]);
        }
        TC_FENCE_BEFORE();
    }

    // ---- epilogue ----
    {
        float inv = 1.0f / l;
        float* Op = O + (rowbase + (size_t)qt * AQ + row) * EMB + h * HDIM + half * 32;
#pragma unroll
        for (int j = 0; j < 8; j++)
            *(float4*)(Op + j * 4) = make_float4(o_acc[4*j] * inv, o_acc[4*j+1] * inv,
                                                 o_acc[4*j+2] * inv, o_acc[4*j+3] * inv);
    }
    __syncthreads();
    if (wid == 0) { TC_RELINQ(); TC_DEALLOC(tmem, 256); }

#else  // ---------------- SIMT fallback attention (non-sm_103a) ---------------
    float* sm = (float*)smem;
    float (*Qts)[128]  = (float (*)[128])sm;
    float (*Vs)[64]    = (float (*)[64])(sm + 64*128);
    float (*Kts)[64]   = (float (*)[64])(sm + 64*128 + 64*64);
    float (*Pts)[128]  = (float (*)[128])(sm + 64*128 + 64*64);

    const int tx = t & 15, ty = t >> 4;
    const float* Qg = Qp + (rowbase + (size_t)qt * 128) * EMB + h * HDIM;
    const float* Kg = Kp + rowbase * EMB + h * HDIM;
    const float* Vg = Vp + rowbase * EMB + h * HDIM;

    const float qscale = 0.125f * 1.44269504088896340736f;
#pragma unroll
    for (int it = 0; it < 8; it++) {
        int idx  = it * 256 + t;
        int qrow = idx >> 4, cg = idx & 15;
        float4 qv = *(const float4*)(Qg + (size_t)qrow * EMB + (cg << 2));
        float qf[4] = {qv.x, qv.y, qv.z, qv.w};
        int col = (((qrow >> 2) ^ cg) << 2) | (qrow & 3);
#pragma unroll
        for (int u = 0; u < 4; u++) Qts[(cg << 2) + u][col] = qscale * qf[u];
    }

    float m[8], l[8], acc[8][4];
#pragma unroll
    for (int i = 0; i < 8; i++) {
        m[i] = -__int_as_float(0x7f800000); l[i] = 0.f;
#pragma unroll
        for (int dd = 0; dd < 4; dd++) acc[i][dd] = 0.f;
    }

    for (int kt = 0; kt < SEQ / 64; kt++) {
        __syncthreads();
#pragma unroll
        for (int it = 0; it < 4; it++) {
            int idx = it * 256 + t;
            int key = idx >> 4, cg = idx & 15;
            float4 kv = *(const float4*)(Kg + (size_t)(kt * 64 + key) * EMB + (cg << 2));
            float kf[4] = {kv.x, kv.y, kv.z, kv.w};
            int col = (((key >> 2) ^ cg) << 2) | (key & 3);
#pragma unroll
            for (int u = 0; u < 4; u++) Kts[(cg << 2) + u][col] = kf[u];
            *(float4*)&Vs[key][cg << 2] =
                *(const float4*)(Vg + (size_t)(kt * 64 + key) * EMB + (cg << 2));
        }
        __syncthreads();

        float s_[8][4];
#pragma unroll
        for (int i = 0; i < 8; i++)
#pragma unroll
            for (int j = 0; j < 4; j++) s_[i][j] = 0.f;
#pragma unroll 8
        for (int d = 0; d < HDIM; d++) {
            int sw = (d >> 2) & 15;
            float4 k4 = *(const float4*)&Kts[d][(tx ^ sw) << 2];
            float4 q0 = *(const float4*)&Qts[d][((2 * ty) ^ sw) << 2];
            float4 q1 = *(const float4*)&Qts[d][((2 * ty + 1) ^ sw) << 2];
            float kf[4]  = {k4.x, k4.y, k4.z, k4.w};
            float q0f[4] = {q0.x, q0.y, q0.z, q0.w};
            float q1f[4] = {q1.x, q1.y, q1.z, q1.w};
#pragma unroll
            for (int i = 0; i < 4; i++)
#pragma unroll
                for (int j = 0; j < 4; j++) {
                    s_[i][j]     += q0f[i] * kf[j];
                    s_[4 + i][j] += q1f[i] * kf[j];
                }
        }

#pragma unroll
        for (int i = 0; i < 8; i++) {
            float mloc = fmaxf(fmaxf(s_[i][0], s_[i][1]), fmaxf(s_[i][2], s_[i][3]));
#pragma unroll
            for (int off = 8; off > 0; off >>= 1)
                mloc = fmaxf(mloc, __shfl_xor_sync(0xffffffffu, mloc, off, 16));
            float mnew = fmaxf(m[i], mloc);
            float corr = ex2f(m[i] - mnew);
            float rsum = 0.f;
#pragma unroll
            for (int j = 0; j < 4; j++) {
                float pv = ex2f(s_[i][j] - mnew);
                s_[i][j] = pv; rsum += pv;
            }
#pragma unroll
            for (int off = 8; off > 0; off >>= 1)
                rsum += __shfl_xor_sync(0xffffffffu, rsum, off, 16);
            l[i] = l[i] * corr + rsum; m[i] = mnew;
#pragma unroll
            for (int dd = 0; dd < 4; dd++) acc[i][dd] *= corr;
        }

        __syncthreads();
#pragma unroll
        for (int j = 0; j < 4; j++) {
            int key = (tx << 2) + j;
            int swp = key & 31;
            *(float4*)&Pts[key][((2 * ty) ^ swp) << 2] =
                make_float4(s_[0][j], s_[1][j], s_[2][j], s_[3][j]);
            *(float4*)&Pts[key][((2 * ty + 1) ^ swp) << 2] =
                make_float4(s_[4][j], s_[5][j], s_[6][j], s_[7][j]);
        }
        __syncthreads();

#pragma unroll 8
        for (int j = 0; j < 64; j++) {
            int swp = j & 31;
            float4 pp0 = *(const float4*)&Pts[j][((2 * ty) ^ swp) << 2];
            float4 pp1 = *(const float4*)&Pts[j][((2 * ty + 1) ^ swp) << 2];
            float4 v4 = *(const float4*)&Vs[j][tx << 2];
            float pf[8] = {pp0.x,pp0.y,pp0.z,pp0.w, pp1.x,pp1.y,pp1.z,pp1.w};
            float vf[4] = {v4.x, v4.y, v4.z, v4.w};
#pragma unroll
            for (int i = 0; i < 8; i++)
#pragma unroll
                for (int dd = 0; dd < 4; dd++)
                    acc[i][dd] += pf[i] * vf[dd];
        }
    }

#pragma unroll
    for (int i = 0; i < 8; i++) {
        float inv = 1.0f / l[i];
        int r = qt * 128 + (ty << 3) + i;
        *(float4*)(O + (rowbase + r) * EMB + h * HDIM + (tx << 2)) =
            make_float4(acc[i][0]*inv, acc[i][1]*inv, acc[i][2]*inv, acc[i][3]*inv);
    }
#endif
}

// ---------------------------------------------------------------------------
extern "C" void kernel_launch(void* const* d_in, const int* in_sizes, int n_in,
                              void* d_out, int out_size) {
    const float* query = (const float*)d_in[0];
    const float* key   = (const float*)d_in[1];
    const float* value = (const float*)d_in[2];
    const float* Wq    = (const float*)d_in[3];
    const float* Wk    = (const float*)d_in[4];
    const float* Wv    = (const float*)d_in[5];
    const float* Wo    = (const float*)d_in[6];
    float* out = (float*)d_out;

    float *q, *k, *v, *ctx;
    cudaGetSymbolAddress((void**)&q,   g_q);
    cudaGetSymbolAddress((void**)&k,   g_k);
    cudaGetSymbolAddress((void**)&v,   g_v);
    cudaGetSymbolAddress((void**)&ctx, g_ctx);

    cudaFuncSetAttribute(gemm_tc_kernel,
                         cudaFuncAttributeMaxDynamicSharedMemorySize, GSMEM);
    cudaFuncSetAttribute(attention_kernel,
                         cudaFuncAttributeMaxDynamicSharedMemorySize, ASMEM);

    dim3 gg(EMB / 128, MTOT / 128);
    gemm_tc_kernel<<<gg, 256, GSMEM>>>(query, Wq, q);
    gemm_tc_kernel<<<gg, 256, GSMEM>>>(key,   Wk, k);
    gemm_tc_kernel<<<gg, 256, GSMEM>>>(value, Wv, v);
    attention_kernel<<<dim3(SEQ / AQ, NHEAD, BATCH), 256, ASMEM>>>(q, k, v, ctx);
    gemm_tc_kernel<<<gg, 256, GSMEM>>>(ctx, Wo, out);
}